// round 5
// baseline (speedup 1.0000x reference)
#include <cuda_runtime.h>

#define FULL 0xffffffffu
typedef unsigned long long ull;

__device__ __forceinline__ float relu_(float v) { return fmaxf(v, 0.0f); }

__device__ __forceinline__ ull ffma2(ull a, ull b, ull c) {
    ull d; asm("fma.rn.f32x2 %0, %1, %2, %3;" : "=l"(d) : "l"(a), "l"(b), "l"(c)); return d;
}
__device__ __forceinline__ ull fadd2(ull a, ull b) {
    ull d; asm("add.rn.f32x2 %0, %1, %2;" : "=l"(d) : "l"(a), "l"(b)); return d;
}
__device__ __forceinline__ ull fmul2(ull a, ull b) {
    ull d; asm("mul.rn.f32x2 %0, %1, %2;" : "=l"(d) : "l"(a), "l"(b)); return d;
}
__device__ __forceinline__ ull pk2(float lo, float hi) {
    ull r; asm("mov.b64 %0, {%1, %2};" : "=l"(r) : "f"(lo), "f"(hi)); return r;
}
__device__ __forceinline__ void upk2(ull v, float& lo, float& hi) {
    asm("mov.b64 {%0, %1}, %2;" : "=f"(lo), "=f"(hi) : "l"(v));
}
__device__ __forceinline__ ull relu2(ull v) {
    float lo, hi; upk2(v, lo, hi);
    return pk2(fmaxf(lo, 0.0f), fmaxf(hi, 0.0f));
}

// ---------------- constant blob layout (floats) ----------------
// [0]    oW1 neuron-pair-major: [t][d][e] = W1[d][2t+e]   (128)
// [128]  ob1 (natural order = neuron pairs)               (32)
// [160]  oW2t [j*32+i]                                    (1024)
// [1184] ob2                                              (32)
// [1216] oW3 [j*16+k]                                     (512)
// [1728] ob3                                              (16)
#define CW_TOTAL 1744
__constant__ __align__(16) float c_w[CW_TOTAL];
__device__   __align__(16) float g_blob[CW_TOTAL];

__global__ void pack_kernel(const float* __restrict__ oW1, const float* __restrict__ ob1,
                            const float* __restrict__ oW2, const float* __restrict__ ob2,
                            const float* __restrict__ oW3, const float* __restrict__ ob3)
{
    int t = threadIdx.x;
    // layer1: [t][d][e] = oW1[d*32 + 2t + e]
    if (t < 128) {
        int tt = t >> 3, d = (t >> 1) & 3, e = t & 1;
        g_blob[t] = oW1[d * 32 + 2 * tt + e];
    }
    if (t < 32) g_blob[128 + t] = ob1[t];
    for (int idx = t; idx < 1024; idx += 256) {
        int j = idx >> 5, i = idx & 31;
        g_blob[160 + j * 32 + i] = oW2[i * 32 + j];
    }
    if (t < 32) g_blob[1184 + t] = ob2[t];
    for (int idx = t; idx < 512; idx += 256) g_blob[1216 + idx] = oW3[idx];
    if (t < 16) g_blob[1728 + t] = ob3[t];
}

// One warp handles TWO batch rows; lane = agent. Main MLP weights on the
// constant/uniform port; row-packed f32x2 tail with dup'd shared tables.
__global__ __launch_bounds__(256, 2)
void dqv_kernel(const float* __restrict__ x,
                const int*   __restrict__ selp,
                const float* __restrict__ sW1, const float* __restrict__ sb1,
                const float* __restrict__ sW2, const float* __restrict__ sb2,
                const float* __restrict__ sW3, const float* __restrict__ sb3,
                const float* __restrict__ gW1, const float* __restrict__ gb1,
                const float* __restrict__ gW2, const float* __restrict__ gb2,
                float* __restrict__ out_q)
{
    __shared__ __align__(16) float s_sW1t[32 * 4];  // [n][d]
    __shared__             float s_sb1[32];
    __shared__ __align__(16) ull  s_sW2d[32 * 32];  // [i][n] dup'd
    __shared__             float s_sb2[32];
    __shared__ __align__(16) ull  s_sW3d[32 * 16];  // [j][k] dup'd
    __shared__             float s_sb3[16];
    __shared__ __align__(16) ull  s_gW1d[32 * 32];  // [c][m] dup'd
    __shared__             float s_gb1[32];
    __shared__ __align__(16) ull  s_gW2d[64];       // [m][a] dup'd
    __shared__             float s_gb2[2];

    const int tid = threadIdx.x;

    for (int idx = tid; idx < 128; idx += 256) {
        int d = idx >> 5, n = idx & 31;
        s_sW1t[n * 4 + d] = sW1[idx];
    }
    for (int idx = tid; idx < 1024; idx += 256) {
        float w2v = sW2[idx];  // [i][n] row-major already
        s_sW2d[idx] = pk2(w2v, w2v);
        float g1v = gW1[idx];  // [c][m] row-major already
        s_gW1d[idx] = pk2(g1v, g1v);
    }
    for (int idx = tid; idx < 512; idx += 256) {
        float w3v = sW3[idx];
        s_sW3d[idx] = pk2(w3v, w3v);
    }
    if (tid < 32) { s_sb1[tid] = sb1[tid]; s_sb2[tid] = sb2[tid]; s_gb1[tid] = gb1[tid]; }
    if (tid >= 48 && tid < 64)  s_sb3[tid - 48] = sb3[tid - 48];
    if (tid >= 64 && tid < 128) { float v = gW2[tid - 64]; s_gW2d[tid - 64] = pk2(v, v); }
    if (tid >= 128 && tid < 130) s_gb2[tid - 128] = gb2[tid - 128];
    __syncthreads();

    const int lane = tid & 31;
    const int warp = tid >> 5;
    const int row0 = blockIdx.x * 16 + warp;
    const int row1 = row0 + 8;
    const int sel  = selp[0];

    const float4 xa0 = reinterpret_cast<const float4*>(x)[row0 * 32 + lane];
    const float4 xa1 = reinterpret_cast<const float4*>(x)[row1 * 32 + lane];

    // ---------------- layer 1: neuron-pair packed FFMA2 ----------------
    ull x0d[4] = { pk2(xa0.x, xa0.x), pk2(xa0.y, xa0.y), pk2(xa0.z, xa0.z), pk2(xa0.w, xa0.w) };
    ull x1d[4] = { pk2(xa1.x, xa1.x), pk2(xa1.y, xa1.y), pk2(xa1.z, xa1.z), pk2(xa1.w, xa1.w) };

    ull h1a[16], h1b[16];   // (h1[2t], h1[2t+1]) per row
    {
        const ulonglong2* w1 = reinterpret_cast<const ulonglong2*>(c_w);   // [t*2 + half]
        const ull* b1 = reinterpret_cast<const ull*>(c_w + 128);
        #pragma unroll
        for (int t = 0; t < 16; ++t) {
            ulonglong2 wA = w1[2 * t + 0];   // d=0,1 neuron-pairs
            ulonglong2 wB = w1[2 * t + 1];   // d=2,3
            ull bb = b1[t];
            ull a0 = ffma2(x0d[0], wA.x, bb);
            a0 = ffma2(x0d[1], wA.y, a0);
            a0 = ffma2(x0d[2], wB.x, a0);
            a0 = ffma2(x0d[3], wB.y, a0);
            h1a[t] = relu2(a0);
            ull a1 = ffma2(x1d[0], wA.x, bb);
            a1 = ffma2(x1d[1], wA.y, a1);
            a1 = ffma2(x1d[2], wB.x, a1);
            a1 = ffma2(x1d[3], wB.y, a1);
            h1b[t] = relu2(a1);
        }
    }

    ull accA[8], accB[8];
    {
        const ull* b3 = reinterpret_cast<const ull*>(c_w + 1728);
        #pragma unroll
        for (int t = 0; t < 8; ++t) { accA[t] = b3[t]; accB[t] = b3[t]; }
    }

    // ---------------- layer 2 + layer 3 fused (K-packed, unchanged) ----------------
    #pragma unroll 4
    for (int j = 0; j < 32; ++j) {
        ull a0 = 0ull, a1 = 0ull;
        const ulonglong2* w2 = reinterpret_cast<const ulonglong2*>(c_w + 160 + j * 32);
        #pragma unroll
        for (int q = 0; q < 8; ++q) {
            ulonglong2 w = w2[q];
            a0 = ffma2(h1a[2 * q + 0], w.x, a0);
            a0 = ffma2(h1a[2 * q + 1], w.y, a0);
            a1 = ffma2(h1b[2 * q + 0], w.x, a1);
            a1 = ffma2(h1b[2 * q + 1], w.y, a1);
        }
        float bj = c_w[1184 + j];
        float l0, h0, l1, h1v;
        upk2(a0, l0, h0);
        upk2(a1, l1, h1v);
        float s0 = relu_(l0 + h0 + bj);
        float s1 = relu_(l1 + h1v + bj);
        ull p0 = pk2(s0, s0);
        ull p1 = pk2(s1, s1);

        const ulonglong2* w3 = reinterpret_cast<const ulonglong2*>(c_w + 1216 + j * 16);
        #pragma unroll
        for (int r = 0; r < 4; ++r) {
            ulonglong2 w = w3[r];
            accA[2 * r + 0] = ffma2(p0, w.x, accA[2 * r + 0]);
            accA[2 * r + 1] = ffma2(p0, w.y, accA[2 * r + 1]);
            accB[2 * r + 0] = ffma2(p1, w.x, accB[2 * r + 0]);
            accB[2 * r + 1] = ffma2(p1, w.y, accB[2 * r + 1]);
        }
    }

    // prefetch selected-agent inputs (hide LDG latency under reduce)
    const float4 xs0 = reinterpret_cast<const float4*>(x)[row0 * 32 + sel];
    const float4 xs1 = reinterpret_cast<const float4*>(x)[row1 * 32 + sel];

    // final relu + mask + packed butterfly reduce
    const float msk = (lane == sel) ? 0.0f : 1.0f;
    #pragma unroll
    for (int t = 0; t < 8; ++t) {
        float lo, hi;
        upk2(accA[t], lo, hi);
        accA[t] = pk2(relu_(lo) * msk, relu_(hi) * msk);
        upk2(accB[t], lo, hi);
        accB[t] = pk2(relu_(lo) * msk, relu_(hi) * msk);
    }
    #pragma unroll
    for (int off = 16; off; off >>= 1) {
        #pragma unroll
        for (int t = 0; t < 8; ++t) {
            accA[t] = fadd2(accA[t], __shfl_xor_sync(FULL, accA[t], off));
            accB[t] = fadd2(accB[t], __shfl_xor_sync(FULL, accB[t], off));
        }
    }

    // transpose K-packed sums into row-packed so_p[c] = (so_row0[c], so_row1[c])
    ull so_p[16];
    #pragma unroll
    for (int r = 0; r < 8; ++r) {
        float a_lo, a_hi, b_lo, b_hi;
        upk2(accA[r], a_lo, a_hi);
        upk2(accB[r], b_lo, b_hi);
        so_p[2 * r + 0] = pk2(a_lo, b_lo);
        so_p[2 * r + 1] = pk2(a_hi, b_hi);
    }

    // ---------------- row-packed tail: sel MLP + gating ----------------
    ull xsp[4] = { pk2(xs0.x, xs1.x), pk2(xs0.y, xs1.y), pk2(xs0.z, xs1.z), pk2(xs0.w, xs1.w) };

    // sel layer1: lane = neuron
    float4 w1v = reinterpret_cast<const float4*>(s_sW1t)[lane];
    {
        float b = s_sb1[lane];
        ull a = pk2(b, b);
        a = ffma2(xsp[0], pk2(w1v.x, w1v.x), a);
        a = ffma2(xsp[1], pk2(w1v.y, w1v.y), a);
        a = ffma2(xsp[2], pk2(w1v.z, w1v.z), a);
        a = ffma2(xsp[3], pk2(w1v.w, w1v.w), a);
        w1v.x = 0.f;   // (dead)
        xsp[0] = relu2(a);   // reuse xsp[0] as sh1p
    }
    const ull sh1p = xsp[0];

    // sel layer2: lane = neuron, shuffle packed activations
    ull a2p;
    {
        float b = s_sb2[lane];
        a2p = pk2(b, b);
        #pragma unroll
        for (int i = 0; i < 32; ++i) {
            ull sv = __shfl_sync(FULL, sh1p, i);
            a2p = ffma2(sv, s_sW2d[i * 32 + lane], a2p);
        }
    }
    const ull sh2p = relu2(a2p);

    // sel layer3: lanes k and k+16 compute component k
    const int k15 = lane & 15;
    ull a3p;
    {
        float b = s_sb3[k15];
        a3p = pk2(b, b);
        #pragma unroll
        for (int j = 0; j < 32; ++j) {
            ull sv = __shfl_sync(FULL, sh2p, j);
            a3p = ffma2(sv, s_sW3d[j * 16 + k15], a3p);
        }
    }
    const ull sel_out_p = relu2(a3p);

    // gating hidden: lane = neuron m; concat = [sel_out(16), sum_other(16)]
    ull agp;
    {
        float b = s_gb1[lane];
        agp = pk2(b, b);
        #pragma unroll
        for (int c = 0; c < 16; ++c) {
            ull sv = __shfl_sync(FULL, sel_out_p, c);
            agp = ffma2(sv, s_gW1d[c * 32 + lane], agp);
        }
        #pragma unroll
        for (int c = 0; c < 16; ++c)
            agp = ffma2(so_p[c], s_gW1d[(16 + c) * 32 + lane], agp);
    }
    const ull hgp = relu2(agp);

    ull q0p = fmul2(hgp, s_gW2d[lane * 2 + 0]);
    ull q1p = fmul2(hgp, s_gW2d[lane * 2 + 1]);
    #pragma unroll
    for (int off = 16; off; off >>= 1) {
        q0p = fadd2(q0p, __shfl_xor_sync(FULL, q0p, off));
        q1p = fadd2(q1p, __shfl_xor_sync(FULL, q1p, off));
    }

    if (lane == 0) {
        float q0r0, q0r1, q1r0, q1r1;
        upk2(q0p, q0r0, q0r1);
        upk2(q1p, q1r0, q1r1);
        int a0 = (int)xs0.w; a0 = a0 < 0 ? 0 : (a0 > 1 ? 1 : a0);
        int a1 = (int)xs1.w; a1 = a1 < 0 ? 0 : (a1 > 1 ? 1 : a1);
        out_q[row0] = a0 ? (q1r0 + s_gb2[1]) : (q0r0 + s_gb2[0]);
        out_q[row1] = a1 ? (q1r1 + s_gb2[1]) : (q0r1 + s_gb2[0]);
    }
}

extern "C" void kernel_launch(void* const* d_in, const int* in_sizes, int n_in,
                              void* d_out, int out_size)
{
    (void)in_sizes; (void)n_in; (void)out_size;

    pack_kernel<<<1, 256>>>(
        (const float*)d_in[2], (const float*)d_in[3],
        (const float*)d_in[4], (const float*)d_in[5],
        (const float*)d_in[6], (const float*)d_in[7]);

    void* dst = nullptr;
    void* src = nullptr;
    cudaGetSymbolAddress(&dst, c_w);
    cudaGetSymbolAddress(&src, g_blob);
    cudaMemcpyAsync(dst, src, CW_TOTAL * sizeof(float),
                    cudaMemcpyDeviceToDevice, 0);

    dqv_kernel<<<4096, 256>>>(
        (const float*)d_in[0],  (const int*)d_in[1],
        (const float*)d_in[8],  (const float*)d_in[9],
        (const float*)d_in[10], (const float*)d_in[11],
        (const float*)d_in[12], (const float*)d_in[13],
        (const float*)d_in[14], (const float*)d_in[15],
        (const float*)d_in[16], (const float*)d_in[17],
        (float*)d_out);
}